// round 8
// baseline (speedup 1.0000x reference)
#include <cuda_runtime.h>
#include <cstdint>

// Shapes (fixed by the problem)
#define S_IN   2048
#define S_T    2048
#define BATCH  8
#define HID    64

#define TM     16            // t-rows per CTA
#define SC     256           // s-chunk size
#define NCHUNK (S_IN / SC)   // 8
#define BPITCH 264           // sBT pitch (floats), 256 + 8 pad
#define LPITCH 68            // staging pitch for sWT (linear stage)
#define THREADS 512

// SMEM layout (floats):
//   sS  [TM][2048]       scores            32768
//   sBT [64][BPITCH]     input^T chunk     16896
//   sAT [64][16]         lin out (h-major)  1024
#define SS_FLOATS  (TM * S_IN)
#define BT_FLOATS  (HID * BPITCH)
#define AT_FLOATS  (HID * 16)
#define SMEM_FLOATS (SS_FLOATS + BT_FLOATS + AT_FLOATS)

typedef unsigned long long ull;

__device__ __forceinline__ ull pack_dup(float x) {
    ull r; asm("mov.b64 %0, {%1, %2};" : "=l"(r) : "f"(x), "f"(x)); return r;
}
__device__ __forceinline__ void unpack2(ull v, float& lo, float& hi) {
    asm("mov.b64 {%0, %1}, %2;" : "=f"(lo), "=f"(hi) : "l"(v));
}
__device__ __forceinline__ void fma2(ull& acc, ull a, ull b) {
    asm("fma.rn.f32x2 %0, %1, %2, %0;" : "+l"(acc) : "l"(a), "l"(b));
}

__device__ __forceinline__ float warp_sum(float v) {
    v += __shfl_xor_sync(0xffffffffu, v, 16);
    v += __shfl_xor_sync(0xffffffffu, v, 8);
    v += __shfl_xor_sync(0xffffffffu, v, 4);
    v += __shfl_xor_sync(0xffffffffu, v, 2);
    v += __shfl_xor_sync(0xffffffffu, v, 1);
    return v;
}
__device__ __forceinline__ float warp_max(float v) {
    v = fmaxf(v, __shfl_xor_sync(0xffffffffu, v, 16));
    v = fmaxf(v, __shfl_xor_sync(0xffffffffu, v, 8));
    v = fmaxf(v, __shfl_xor_sync(0xffffffffu, v, 4));
    v = fmaxf(v, __shfl_xor_sync(0xffffffffu, v, 2));
    v = fmaxf(v, __shfl_xor_sync(0xffffffffu, v, 1));
    return v;
}

__global__ void __launch_bounds__(THREADS, 1)
attn_fused_kernel(const float* __restrict__ inp,        // (S_IN, B, H)
                  const float* __restrict__ tgt,        // (S_T, B, H)
                  const unsigned char* __restrict__ msk,// (B, S_T, S_IN) bool
                  const float* __restrict__ Wm,         // (H, H)  W[o][h]
                  const float* __restrict__ bias,       // (H)
                  float* __restrict__ out)              // (B, S_T, S_IN)
{
    extern __shared__ float sm[];
    float* sS  = sm;                        // TM * 2048
    float* sBT = sm + SS_FLOATS;            // [h][s] transposed input chunk
    float* sAT = sBT + BT_FLOATS;           // [h][r] linear output, transposed

    const int tid = threadIdx.x;
    const int b   = blockIdx.x >> 7;          // 8 batches
    const int t0  = (blockIdx.x & 127) << 4;  // tile of 16 t-rows

    // thread -> (s-row, h-half) for chunk staging; warp lanes share one half
    const int srow = tid & 255;     // s index within chunk
    const int half = tid >> 8;      // 0: h 0..31, 1: h 32..63

    // ---------------- prefetch chunk 0 into registers ----------------
    float4 pf[8];
    {
        const float4* src = reinterpret_cast<const float4*>(
            inp + ((size_t)(srow * BATCH + b)) * HID + half * 32);
        #pragma unroll
        for (int i = 0; i < 8; ++i) pf[i] = src[i];
    }

    // ---------------- stage W (transposed) + target tile in sS region ----------------
    float* sWT = sS;                  // 64 * LPITCH floats
    float* sTg = sS + HID * LPITCH;   // TM * 64 floats
    if (tid < 256) {
        const int o  = tid >> 2;
        const int hq = (tid & 3) * 16;
        #pragma unroll
        for (int k = 0; k < 4; ++k) {
            float4 wv = *reinterpret_cast<const float4*>(Wm + o * HID + hq + 4 * k);
            sWT[(hq + 4 * k + 0) * LPITCH + o] = wv.x;
            sWT[(hq + 4 * k + 1) * LPITCH + o] = wv.y;
            sWT[(hq + 4 * k + 2) * LPITCH + o] = wv.z;
            sWT[(hq + 4 * k + 3) * LPITCH + o] = wv.w;
        }
        const int r  = tid >> 4;
        const int hh = (tid & 15) * 4;
        *reinterpret_cast<float4*>(sTg + r * HID + hh) =
            *reinterpret_cast<const float4*>(tgt + ((size_t)((t0 + r) * BATCH + b)) * HID + hh);
    }
    __syncthreads();

    // ---------------- sAT[o][r] = (target_tile @ W^T + bias)[r][o] ----------------
    if (tid < 256) {
        const int r  = tid >> 4;
        const int o0 = (tid & 15) * 4;
        float4 acc = *reinterpret_cast<const float4*>(bias + o0);
        #pragma unroll
        for (int h = 0; h < HID; ++h) {
            const float  tv = sTg[r * HID + h];
            const float4 wv = *reinterpret_cast<const float4*>(sWT + h * LPITCH + o0);
            acc.x += tv * wv.x;
            acc.y += tv * wv.y;
            acc.z += tv * wv.z;
            acc.w += tv * wv.w;
        }
        sAT[(o0 + 0) * 16 + r] = acc.x;
        sAT[(o0 + 1) * 16 + r] = acc.y;
        sAT[(o0 + 2) * 16 + r] = acc.z;
        sAT[(o0 + 3) * 16 + r] = acc.w;
    }
    // (loop-top __syncthreads() makes sAT visible before first use)

    const int wid  = tid >> 5;
    const int lane = tid & 31;
    const int rg   = wid >> 3;                  // row group: rows rg*8 .. rg*8+7
    const int col  = (wid & 7) * 32 + lane;     // s-col within chunk (0..255)

    // ---------------- main loop over s-chunks ----------------
    for (int c = 0; c < NCHUNK; ++c) {
        __syncthreads();   // prev compute done reading sBT; sAT visible (c==0)
        // transpose-store prefetched chunk into sBT[h][s] (lanes: consecutive s, same h)
        #pragma unroll
        for (int i = 0; i < 8; ++i) {
            const int h0 = half * 32 + 4 * i;
            sBT[(h0 + 0) * BPITCH + srow] = pf[i].x;
            sBT[(h0 + 1) * BPITCH + srow] = pf[i].y;
            sBT[(h0 + 2) * BPITCH + srow] = pf[i].z;
            sBT[(h0 + 3) * BPITCH + srow] = pf[i].w;
        }
        __syncthreads();
        // prefetch next chunk (latency hidden by compute below)
        if (c + 1 < NCHUNK) {
            const float4* src = reinterpret_cast<const float4*>(
                inp + ((size_t)(((c + 1) * SC + srow) * BATCH + b)) * HID + half * 32);
            #pragma unroll
            for (int i = 0; i < 8; ++i) pf[i] = src[i];
        }

        // 8 rows x 1 col per lane; rows paired into f32x2 accumulators
        ull acc0 = 0ull, acc1 = 0ull, acc2 = 0ull, acc3 = 0ull;
        const float* aBase = sAT + rg * 8;
        const float* bCol  = sBT + col;
        #pragma unroll
        for (int h = 0; h < HID; ++h) {
            const ulonglong2 aP = *reinterpret_cast<const ulonglong2*>(aBase + h * 16);     // rows +0..3
            const ulonglong2 aQ = *reinterpret_cast<const ulonglong2*>(aBase + h * 16 + 4); // rows +4..7
            const ull bb = pack_dup(bCol[h * BPITCH]);
            fma2(acc0, aP.x, bb);
            fma2(acc1, aP.y, bb);
            fma2(acc2, aQ.x, bb);
            fma2(acc3, aQ.y, bb);
        }
        // store scores (consecutive lanes -> consecutive cols, conflict-free)
        float* dst = sS + c * SC + col;
        float lo, hi;
        unpack2(acc0, lo, hi);
        dst[(rg * 8 + 0) * S_IN] = lo;  dst[(rg * 8 + 1) * S_IN] = hi;
        unpack2(acc1, lo, hi);
        dst[(rg * 8 + 2) * S_IN] = lo;  dst[(rg * 8 + 3) * S_IN] = hi;
        unpack2(acc2, lo, hi);
        dst[(rg * 8 + 4) * S_IN] = lo;  dst[(rg * 8 + 5) * S_IN] = hi;
        unpack2(acc3, lo, hi);
        dst[(rg * 8 + 6) * S_IN] = lo;  dst[(rg * 8 + 7) * S_IN] = hi;
    }
    __syncthreads();

    // ---------------- register-resident epilogue: one warp per row ----------------
    // mean -> abs/mask -> max -> exp -> normalize, single SMEM read pass
    {
        const float NEG_INF = __int_as_float(0xff800000);
        const int r = wid;                           // 16 warps, 16 rows
        const float* row = sS + r * S_IN;
        const size_t gbase = ((size_t)(b * S_T + (t0 + r))) * S_IN;

        // load full row into registers (64 regs) + sum
        float4 v[16];
        float s = 0.f;
        #pragma unroll
        for (int i = 0; i < 16; ++i) {
            v[i] = *reinterpret_cast<const float4*>(row + i * 128 + lane * 4);
            s += (v[i].x + v[i].y) + (v[i].z + v[i].w);
        }
        s = warp_sum(s);
        const float mean = s * (1.0f / 2048.0f);

        // y = |x - mean|, apply mask (-inf), track max (all in registers)
        float m = NEG_INF;
        #pragma unroll
        for (int i = 0; i < 16; ++i) {
            const unsigned int mk = *reinterpret_cast<const unsigned int*>(
                msk + gbase + i * 128 + lane * 4);
            v[i].x = fabsf(v[i].x - mean);
            v[i].y = fabsf(v[i].y - mean);
            v[i].z = fabsf(v[i].z - mean);
            v[i].w = fabsf(v[i].w - mean);
            if (mk & 0x000000FFu) v[i].x = NEG_INF;
            if (mk & 0x0000FF00u) v[i].y = NEG_INF;
            if (mk & 0x00FF0000u) v[i].z = NEG_INF;
            if (mk & 0xFF000000u) v[i].w = NEG_INF;
            m = fmaxf(m, fmaxf(fmaxf(v[i].x, v[i].y), fmaxf(v[i].z, v[i].w)));
        }
        m = warp_max(m);

        // e = exp(y - max); sum
        float l = 0.f;
        #pragma unroll
        for (int i = 0; i < 16; ++i) {
            v[i].x = __expf(v[i].x - m);
            v[i].y = __expf(v[i].y - m);
            v[i].z = __expf(v[i].z - m);
            v[i].w = __expf(v[i].w - m);
            l += (v[i].x + v[i].y) + (v[i].z + v[i].w);
        }
        l = warp_sum(l);
        const float inv = 1.0f / l;

        // write normalized probabilities straight to GMEM
        #pragma unroll
        for (int i = 0; i < 16; ++i) {
            v[i].x *= inv; v[i].y *= inv; v[i].z *= inv; v[i].w *= inv;
            *reinterpret_cast<float4*>(out + gbase + i * 128 + lane * 4) = v[i];
        }
    }
}

extern "C" void kernel_launch(void* const* d_in, const int* in_sizes, int n_in,
                              void* d_out, int out_size)
{
    const float*         inp  = (const float*)d_in[0];
    const float*         tgt  = (const float*)d_in[1];
    const unsigned char* msk  = (const unsigned char*)d_in[2];
    const float*         Wm   = (const float*)d_in[3];
    const float*         bias = (const float*)d_in[4];
    float*               out  = (float*)d_out;

    const int smem_bytes = SMEM_FLOATS * (int)sizeof(float); // 202752 B
    cudaFuncSetAttribute(attn_fused_kernel,
                         cudaFuncAttributeMaxDynamicSharedMemorySize, smem_bytes);

    dim3 grid(BATCH * (S_T / TM));  // 1024 CTAs
    dim3 block(THREADS);
    attn_fused_kernel<<<grid, block, smem_bytes>>>(inp, tgt, msk, Wm, bias, out);
}